// round 17
// baseline (speedup 1.0000x reference)
#include <cuda_runtime.h>
#include <math.h>

#define BB 256
#define LL 512
#define HH 64
#define NHEAD 2
#define HDIM 32
#define VV 64
#define KSLOT 8

typedef unsigned long long u64;
typedef unsigned int u32;

// -------------------- scratch (device globals; no runtime alloc) ------------
__device__ float g_q [BB*NHEAD*LL*HDIM];
__device__ float g_k [BB*NHEAD*LL*HDIM];
__device__ float g_v [BB*NHEAD*LL*HDIM];
__device__ float g_ao[BB*LL*HH];
__device__ float g_h2[BB*LL*HH];
__device__ float g_gs[BB*LL];
__device__ float g_tl[BB];

// -------------------- packed f32x2 helpers ----------------------------------
__device__ __forceinline__ u64 pack2(float x, float y) {
    u64 r; asm("mov.b64 %0,{%1,%2};" : "=l"(r) : "f"(x), "f"(y)); return r;
}
__device__ __forceinline__ void unpack2(u64 v, float& x, float& y) {
    asm("mov.b64 {%0,%1},%2;" : "=f"(x), "=f"(y) : "l"(v));
}
__device__ __forceinline__ u64 ffma2(u64 a, u64 b, u64 c) {
    u64 d; asm("fma.rn.f32x2 %0,%1,%2,%3;" : "=l"(d) : "l"(a), "l"(b), "l"(c));
    return d;
}
__device__ __forceinline__ float warp_sum(float v) {
#pragma unroll
    for (int o = 16; o; o >>= 1) v += __shfl_xor_sync(0xffffffffu, v, o);
    return v;
}
__device__ __forceinline__ float warp_max(float v) {
#pragma unroll
    for (int o = 16; o; o >>= 1) v = fmaxf(v, __shfl_xor_sync(0xffffffffu, v, o));
    return v;
}

// -------------------- fast packed exp (fma/alu pipes) ------------------------
struct ExpC { u64 L2, MG, N1, C5, C4, C3, C2, C1, C0; };
__device__ __forceinline__ ExpC expc_make() {
    ExpC E;
    E.L2 = pack2(1.4426950408889634f, 1.4426950408889634f);
    E.MG = pack2(12582912.f, 12582912.f);
    E.N1 = pack2(-1.f, -1.f);
    E.C5 = pack2(1.3333558146428443e-3f, 1.3333558146428443e-3f);
    E.C4 = pack2(9.618129107628477e-3f, 9.618129107628477e-3f);
    E.C3 = pack2(5.550410866482158e-2f, 5.550410866482158e-2f);
    E.C2 = pack2(2.402265069591007e-1f, 2.402265069591007e-1f);
    E.C1 = pack2(6.931471805599453e-1f, 6.931471805599453e-1f);
    E.C0 = pack2(1.f, 1.f);
    return E;
}
__device__ __forceinline__ void fexp2(const ExpC& E, float s0, float s1,
                                      float& p0, float& p1) {
    u64 sp = pack2(s0, s1);
    u64 r = ffma2(sp, E.L2, E.MG);
    u64 t = ffma2(r, E.N1, E.MG);
    u64 f = ffma2(sp, E.L2, t);
    u64 a = ffma2(E.C5, f, E.C4);
    a = ffma2(a, f, E.C3);
    a = ffma2(a, f, E.C2);
    a = ffma2(a, f, E.C1);
    a = ffma2(a, f, E.C0);
    float r0, r1, a0, a1;
    unpack2(r, r0, r1); unpack2(a, a0, a1);
    p0 = a0 * __int_as_float((__float_as_int(r0) + (127 - 0x4B400000)) << 23);
    p1 = a1 * __int_as_float((__float_as_int(r1) + (127 - 0x4B400000)) << 23);
}

// -------------------- mma helpers -------------------------------------------
__device__ __forceinline__ u32 f2tf32(float f) {
    u32 r; asm("cvt.rna.tf32.f32 %0, %1;" : "=r"(r) : "f"(f)); return r;
}
__device__ __forceinline__ void mma_tf32(float& c0, float& c1, float& c2, float& c3,
                                         u32 a0, u32 a1, u32 a2, u32 a3,
                                         u32 b0, u32 b1) {
    asm volatile(
        "mma.sync.aligned.m16n8k8.row.col.f32.tf32.tf32.f32 "
        "{%0,%1,%2,%3}, {%4,%5,%6,%7}, {%8,%9}, {%0,%1,%2,%3};"
        : "+f"(c0), "+f"(c1), "+f"(c2), "+f"(c3)
        : "r"(a0), "r"(a1), "r"(a2), "r"(a3), "r"(b0), "r"(b1));
}

__device__ __forceinline__ float* qkv_ptr(int t, int o) {
    int b = t >> 9, l = t & 511;
    int oo = o & 63;
    float* base = (o < 64) ? g_q : ((o < 128) ? g_k : g_v);
    return base + (((size_t)(b * 2 + (oo >> 5))) * 512 + l) * 32 + (oo & 31);
}

// -------------------- K1: embed gather + QKV via tf32 mma --------------------
#define K1_SMW (192*68 + 256*68 + 192)
__global__ void __launch_bounds__(512, 1) k1_embed_qkv(
        const float* __restrict__ embed, const float* __restrict__ W_in,
        const float* __restrict__ b_in, const int* __restrict__ seq) {
    extern __shared__ u32 smk[];
    u32* Wb = smk;                    // 192*68
    u32* hb = smk + 192*68;           // 256*68
    float* bs = (float*)(smk + 192*68 + 256*68);  // 192
    int tid = threadIdx.x;
    for (int i = tid; i < 192*64; i += 512) {
        int n = i >> 6, j = i & 63;
        int dst = n * 68 + (j & ~7) + ((j & 3) << 1) + ((j >> 2) & 1);
        Wb[dst] = f2tf32(W_in[i]);
    }
    if (tid < 192) bs[tid] = b_in[tid];
    int t0 = blockIdx.x * 256;
    for (int i = tid; i < 256*64; i += 512) {
        int row = i >> 6, col = i & 63;
        int tok = seq[t0 + row];
        hb[row * 68 + col] = f2tf32(embed[(size_t)tok * 64 + col]);
    }
    __syncthreads();

    int warp = tid >> 5, lane = tid & 31, qr = lane >> 2, qc = lane & 3;
    int rb = warp * 16;
    int rows[2] = {rb + qr, rb + qr + 8};
    u32 af[8][4];
#pragma unroll
    for (int kk = 0; kk < 8; kk++) {
        af[kk][0] = hb[rows[0] * 68 + kk * 8 + qc];
        af[kk][1] = hb[rows[1] * 68 + kk * 8 + qc];
        af[kk][2] = hb[rows[0] * 68 + kk * 8 + qc + 4];
        af[kk][3] = hb[rows[1] * 68 + kk * 8 + qc + 4];
    }
#pragma unroll 2
    for (int n8 = 0; n8 < 24; n8++) {
        float c0[4] = {0.f, 0.f, 0.f, 0.f};
        int wrow = (n8 * 8 + qr) * 68 + 2 * qc;
#pragma unroll
        for (int kk = 0; kk < 8; kk++) {
            uint2 bh = *(const uint2*)(Wb + wrow + kk * 8);
            mma_tf32(c0[0], c0[1], c0[2], c0[3],
                     af[kk][0], af[kk][1], af[kk][2], af[kk][3],
                     bh.x, bh.y);
        }
        int o0 = n8 * 8 + 2 * qc;
        float bb0 = bs[o0], bb1 = bs[o0 + 1];
        *(float2*)qkv_ptr(t0 + rows[0], o0) = make_float2(c0[0] + bb0, c0[1] + bb1);
        *(float2*)qkv_ptr(t0 + rows[1], o0) = make_float2(c0[2] + bb0, c0[3] + bb1);
    }
}

// -------------------- K2: attention via TF32 mma (3 blocks/SM) ---------------
// Grid = 2048: block handles (bh, quarter) = 128 query rows, m=1 tile/warp.
// 74 KB smem/block -> 3 co-resident blocks/SM (24 warps) hide load/sync
// phases under neighbors' mma streams. Softmax accumulates across chunks
// exactly (no rescaling).
#define K2_PAD 36
#define K2_CHROWS 256
#define K2_SMB (2*K2_CHROWS*K2_PAD*4)
__global__ void __launch_bounds__(256, 3) k2_attn() {
    extern __shared__ u32 smu[];
    u32* ksh = smu;                       // 256*36
    u32* vsh = smu + K2_CHROWS * K2_PAD;  // 256*36
    int bh = blockIdx.x >> 2;
    int quarter = blockIdx.x & 3;
    int b = bh >> 1, h = bh & 1;
    int tid = threadIdx.x;
    const float scale = 0.17677669529663687f; // 1/sqrt(32)

    int warp = tid >> 5, lane = tid & 31;
    int qr = lane >> 2, qc = lane & 3;
    int row_base = quarter * 128 + warp * 16;
    const ExpC E = expc_make();

    u32 qf[4][4];
    {
        const float* qg = g_q + ((size_t)bh * LL) * HDIM;
#pragma unroll
        for (int kk = 0; kk < 4; kk++) {
            int r0 = row_base + qr, r1 = r0 + 8;
            int c0 = kk * 8 + qc, c1 = c0 + 4;
            qf[kk][0] = f2tf32(qg[r0 * 32 + c0] * scale);
            qf[kk][1] = f2tf32(qg[r1 * 32 + c0] * scale);
            qf[kk][2] = f2tf32(qg[r0 * 32 + c1] * scale);
            qf[kk][3] = f2tf32(qg[r1 * 32 + c1] * scale);
        }
    }

    float oacc[4][4];
#pragma unroll
    for (int n = 0; n < 4; n++)
#pragma unroll
        for (int r = 0; r < 4; r++) oacc[n][r] = 0.f;
    float osum0 = 0.f, osum1 = 0.f;

    int srcA = (lane & 28) | (qc >> 1);
    int srcB = srcA + 2;
    bool odd = qc & 1;

#pragma unroll 1
    for (int ch = 0; ch < 2; ch++) {
        __syncthreads();
        {
            const float4* kg = (const float4*)(g_k + ((size_t)bh * LL + ch * K2_CHROWS) * HDIM);
            const float4* vg = (const float4*)(g_v + ((size_t)bh * LL + ch * K2_CHROWS) * HDIM);
            for (int i = tid; i < K2_CHROWS * 8; i += 256) {
                int row = i >> 3, c4 = i & 7;
                float4 kv = kg[i];
                float4 vv = vg[i];
                uint4 kb4, vb4;
                kb4.x = f2tf32(kv.x); kb4.y = f2tf32(kv.y);
                kb4.z = f2tf32(kv.z); kb4.w = f2tf32(kv.w);
                vb4.x = f2tf32(vv.x); vb4.y = f2tf32(vv.y);
                vb4.z = f2tf32(vv.z); vb4.w = f2tf32(vv.w);
                *(uint4*)(ksh + row * K2_PAD + c4 * 4) = kb4;
                *(uint4*)(vsh + row * K2_PAD + c4 * 4) = vb4;
            }
        }
        __syncthreads();

#pragma unroll 1
        for (int kb = 0; kb < K2_CHROWS / 8; kb++) {
            u32 kf[4][2];
            const u32* krow = ksh + (kb * 8 + qr) * K2_PAD;
#pragma unroll
            for (int kk = 0; kk < 4; kk++) {
                kf[kk][0] = krow[kk * 8 + qc];
                kf[kk][1] = krow[kk * 8 + qc + 4];
            }
            u32 vf[4][2];
            const u32* vrow0 = vsh + (kb * 8 + qc) * K2_PAD;
            const u32* vrow1 = vsh + (kb * 8 + qc + 4) * K2_PAD;
#pragma unroll
            for (int n = 0; n < 4; n++) {
                vf[n][0] = vrow0[n * 8 + qr];
                vf[n][1] = vrow1[n * 8 + qr];
            }
            float c0 = 0.f, c1 = 0.f, c2 = 0.f, c3 = 0.f;
#pragma unroll
            for (int kk = 0; kk < 4; kk++)
                mma_tf32(c0, c1, c2, c3,
                         qf[kk][0], qf[kk][1], qf[kk][2], qf[kk][3],
                         kf[kk][0], kf[kk][1]);
            float p0, p1, p2, p3;
            fexp2(E, c0, c1, p0, p1);
            fexp2(E, c2, c3, p2, p3);
            osum0 += p0 + p1;
            osum1 += p2 + p3;
            float x0 = __shfl_sync(0xffffffffu, p0, srcA);
            float x1 = __shfl_sync(0xffffffffu, p1, srcA);
            float x2 = __shfl_sync(0xffffffffu, p2, srcA);
            float x3 = __shfl_sync(0xffffffffu, p3, srcA);
            float y0 = __shfl_sync(0xffffffffu, p0, srcB);
            float y1 = __shfl_sync(0xffffffffu, p1, srcB);
            float y2 = __shfl_sync(0xffffffffu, p2, srcB);
            float y3 = __shfl_sync(0xffffffffu, p3, srcB);
            u32 a0 = f2tf32(odd ? x1 : x0);
            u32 a1 = f2tf32(odd ? x3 : x2);
            u32 a2 = f2tf32(odd ? y1 : y0);
            u32 a3 = f2tf32(odd ? y3 : y2);
#pragma unroll
            for (int n = 0; n < 4; n++)
                mma_tf32(oacc[n][0], oacc[n][1], oacc[n][2], oacc[n][3],
                         a0, a1, a2, a3, vf[n][0], vf[n][1]);
        }
    }

    float* aob = g_ao + ((size_t)b * LL) * HH + h * HDIM;
    {
        float s0 = osum0, s1 = osum1;
        s0 += __shfl_xor_sync(0xffffffffu, s0, 1);
        s0 += __shfl_xor_sync(0xffffffffu, s0, 2);
        s1 += __shfl_xor_sync(0xffffffffu, s1, 1);
        s1 += __shfl_xor_sync(0xffffffffu, s1, 2);
        float inv0 = 1.f / s0, inv1 = 1.f / s1;
        int r0 = row_base + qr, r1 = r0 + 8;
#pragma unroll
        for (int n = 0; n < 4; n++) {
            int col = n * 8 + 2 * qc;
            float2 v0 = make_float2(oacc[n][0] * inv0, oacc[n][1] * inv0);
            float2 v1 = make_float2(oacc[n][2] * inv1, oacc[n][3] * inv1);
            *(float2*)(aob + (size_t)r0 * HH + col) = v0;
            *(float2*)(aob + (size_t)r1 * HH + col) = v1;
        }
    }
}

// -------------------- K3: epilogue, 1-pass tf32 (2 tiles/block) --------------
#define SO_WOH 0
#define SO_W1H 4352
#define SO_W2H 13056
#define SO_LMH 21504
#define SO_ACT 25856
#define SO_PRM 34560
#define K3_SMW 35204
__global__ void __launch_bounds__(256, 1) k3_epilogue(
        const float* __restrict__ embed,
        const float* __restrict__ W_out, const float* __restrict__ b_out,
        const float* __restrict__ ln1g, const float* __restrict__ ln1b,
        const float* __restrict__ W1,   const float* __restrict__ b1,
        const float* __restrict__ W2,   const float* __restrict__ b2,
        const float* __restrict__ ln2g, const float* __restrict__ ln2b,
        const float* __restrict__ lmW,  const float* __restrict__ lmb,
        const float* __restrict__ gateW, const float* __restrict__ gateb,
        const int* __restrict__ seq, float* __restrict__ out_tok) {
    extern __shared__ u32 smw[];
    u32* WOH = smw + SO_WOH;
    u32* W1H = smw + SO_W1H;
    u32* W2H = smw + SO_W2H;
    u32* LMH = smw + SO_LMH;
    float* act = (float*)(smw + SO_ACT);
    float* prm = (float*)(smw + SO_PRM);
    int tid = threadIdx.x;
    const ExpC E = expc_make();

    for (int i = tid; i < 4096; i += 256) {
        int n = i >> 6, j = i & 63;
        int dst = n * 68 + (j & ~7) + ((j & 3) << 1) + ((j >> 2) & 1);
        WOH[dst] = f2tf32(W_out[i]);
        LMH[dst] = f2tf32(lmW[i]);
    }
    for (int i = tid; i < 8192; i += 256) {
        int n = i >> 6, j = i & 63;
        W1H[n * 68 + (j & ~7) + ((j & 3) << 1) + ((j >> 2) & 1)] = f2tf32(W1[i]);
        int n2 = i >> 7, j2 = i & 127;
        W2H[n2 * 132 + (j2 & ~7) + ((j2 & 3) << 1) + ((j2 >> 2) & 1)] = f2tf32(W2[i]);
    }
    for (int i = tid; i < 64; i += 256) {
        prm[i] = b_out[i];    prm[192+i] = b2[i];   prm[256+i] = lmb[i];
        prm[320+i] = ln1g[i]; prm[384+i] = ln1b[i];
        prm[448+i] = ln2g[i]; prm[512+i] = ln2b[i];
        prm[576+i] = gateW[i];
    }
    if (tid < 128) prm[64 + tid] = b1[tid];
    if (tid == 0) prm[640] = gateb[0];

    int warp = tid >> 5, lane = tid & 31;
    int qr = lane >> 2, qc = lane & 3;
    int r0 = warp * 16 + qr, r1 = r0 + 8;
    int srcA = (lane & 28) | (qc >> 1);
    int srcB = srcA + 2;
    bool odd = qc & 1;
    int prow = tid >> 1, phalf = tid & 1;

#pragma unroll 1
    for (int tile = 0; tile < 2; tile++) {
        int tbase = blockIdx.x * 256 + tile * 128;
        __syncthreads();
        {
            const float4* aog = (const float4*)(g_ao + (size_t)tbase * 64);
            for (int i = tid; i < 2048; i += 256) {
                int row = i >> 4, c4 = i & 15;
                *(float4*)(act + row * 68 + c4 * 4) = aog[i];
            }
        }
        __syncthreads();

        // ---- S1: C1 = ao @ W_out^T (1-pass tf32) ----
        {
            u32 ah[8][4];
#pragma unroll
            for (int kk = 0; kk < 8; kk++) {
                ah[kk][0] = f2tf32(act[r0 * 68 + kk * 8 + qc]);
                ah[kk][1] = f2tf32(act[r1 * 68 + kk * 8 + qc]);
                ah[kk][2] = f2tf32(act[r0 * 68 + kk * 8 + qc + 4]);
                ah[kk][3] = f2tf32(act[r1 * 68 + kk * 8 + qc + 4]);
            }
            __syncwarp();
#pragma unroll
            for (int n8 = 0; n8 < 8; n8++) {
                float c0 = 0.f, c1 = 0.f, c2 = 0.f, c3 = 0.f;
                int wrow = (n8 * 8 + qr) * 68 + 2 * qc;
#pragma unroll
                for (int kk = 0; kk < 8; kk++) {
                    uint2 bh = *(const uint2*)(WOH + wrow + kk * 8);
                    mma_tf32(c0, c1, c2, c3, ah[kk][0], ah[kk][1], ah[kk][2], ah[kk][3], bh.x, bh.y);
                }
                *(float2*)(act + r0 * 68 + n8 * 8 + 2 * qc) = make_float2(c0, c1);
                *(float2*)(act + r1 * 68 + n8 * 8 + 2 * qc) = make_float2(c2, c3);
            }
        }
        __syncthreads();

        // ---- S2: + b_out + h0, LN1 -> h1 (2 threads/token) ----
        {
            int t = tbase + prow;
            int tok = seq[t];
            float x[32];
            const float4* ar = (const float4*)(act + prow * 68 + phalf * 32);
            const float4* ep = (const float4*)(embed + (size_t)tok * 64 + phalf * 32);
            int pb = phalf * 32;
            float sum = 0.f;
#pragma unroll
            for (int c = 0; c < 8; c++) {
                float4 a = ar[c]; float4 e = ep[c];
                x[4*c]   = a.x + e.x + prm[pb+4*c];
                x[4*c+1] = a.y + e.y + prm[pb+4*c+1];
                x[4*c+2] = a.z + e.z + prm[pb+4*c+2];
                x[4*c+3] = a.w + e.w + prm[pb+4*c+3];
                sum += x[4*c] + x[4*c+1] + x[4*c+2] + x[4*c+3];
            }
            sum += __shfl_xor_sync(0xffffffffu, sum, 1);
            float m = sum * (1.f/64.f);
            float var = 0.f;
#pragma unroll
            for (int j = 0; j < 32; j++) { float d = x[j] - m; var += d * d; }
            var += __shfl_xor_sync(0xffffffffu, var, 1);
            float rstd = rsqrtf(var * (1.f/64.f) + 1e-5f);
            float4* aw = (float4*)(act + prow * 68 + phalf * 32);
#pragma unroll
            for (int c = 0; c < 8; c++) {
                float4 o;
                o.x = (x[4*c]   - m) * rstd * prm[320+pb+4*c]   + prm[384+pb+4*c];
                o.y = (x[4*c+1] - m) * rstd * prm[320+pb+4*c+1] + prm[384+pb+4*c+1];
                o.z = (x[4*c+2] - m) * rstd * prm[320+pb+4*c+2] + prm[384+pb+4*c+2];
                o.w = (x[4*c+3] - m) * rstd * prm[320+pb+4*c+3] + prm[384+pb+4*c+3];
                aw[c] = o;
            }
        }
        __syncthreads();

        // ---- S3: fused FF1(relu)+FF2 (1-pass tf32) ----
        {
            u32 ah[8][4];
#pragma unroll
            for (int kk = 0; kk < 8; kk++) {
                ah[kk][0] = f2tf32(act[r0 * 68 + kk * 8 + qc]);
                ah[kk][1] = f2tf32(act[r1 * 68 + kk * 8 + qc]);
                ah[kk][2] = f2tf32(act[r0 * 68 + kk * 8 + qc + 4]);
                ah[kk][3] = f2tf32(act[r1 * 68 + kk * 8 + qc + 4]);
            }
            __syncwarp();
            float z[8][4];
#pragma unroll
            for (int n = 0; n < 8; n++)
#pragma unroll
                for (int r = 0; r < 4; r++) z[n][r] = 0.f;
#pragma unroll 2
            for (int kk2 = 0; kk2 < 16; kk2++) {
                float y0 = 0.f, y1 = 0.f, y2 = 0.f, y3 = 0.f;
                int w1row = (kk2 * 8 + qr) * 68 + 2 * qc;
#pragma unroll
                for (int kk = 0; kk < 8; kk++) {
                    uint2 bh = *(const uint2*)(W1H + w1row + kk * 8);
                    mma_tf32(y0, y1, y2, y3, ah[kk][0], ah[kk][1], ah[kk][2], ah[kk][3], bh.x, bh.y);
                }
                float bb0 = prm[64 + kk2 * 8 + 2 * qc];
                float bb1 = prm[64 + kk2 * 8 + 2 * qc + 1];
                y0 = fmaxf(y0 + bb0, 0.f); y1 = fmaxf(y1 + bb1, 0.f);
                y2 = fmaxf(y2 + bb0, 0.f); y3 = fmaxf(y3 + bb1, 0.f);
                float x0 = __shfl_sync(0xffffffffu, y0, srcA);
                float x1 = __shfl_sync(0xffffffffu, y1, srcA);
                float x2 = __shfl_sync(0xffffffffu, y2, srcA);
                float x3 = __shfl_sync(0xffffffffu, y3, srcA);
                float w0 = __shfl_sync(0xffffffffu, y0, srcB);
                float w1v = __shfl_sync(0xffffffffu, y1, srcB);
                float w2v = __shfl_sync(0xffffffffu, y2, srcB);
                float w3 = __shfl_sync(0xffffffffu, y3, srcB);
                u32 A0 = f2tf32(odd ? x1 : x0);
                u32 A1 = f2tf32(odd ? x3 : x2);
                u32 A2 = f2tf32(odd ? w1v : w0);
                u32 A3 = f2tf32(odd ? w3 : w2v);
#pragma unroll
                for (int n8 = 0; n8 < 8; n8++) {
                    int w2row = (n8 * 8 + qr) * 132 + kk2 * 8 + 2 * qc;
                    uint2 bh = *(const uint2*)(W2H + w2row);
                    mma_tf32(z[n8][0], z[n8][1], z[n8][2], z[n8][3], A0, A1, A2, A3, bh.x, bh.y);
                }
            }
            __syncwarp();
#pragma unroll
            for (int n8 = 0; n8 < 8; n8++) {
                float2 h1a = *(const float2*)(act + r0 * 68 + n8 * 8 + 2 * qc);
                float2 h1b = *(const float2*)(act + r1 * 68 + n8 * 8 + 2 * qc);
                float bb0 = prm[192 + n8 * 8 + 2 * qc];
                float bb1 = prm[192 + n8 * 8 + 2 * qc + 1];
                float2 s0 = make_float2(z[n8][0] + h1a.x + bb0, z[n8][1] + h1a.y + bb1);
                float2 s1 = make_float2(z[n8][2] + h1b.x + bb0, z[n8][3] + h1b.y + bb1);
                *(float2*)(act + r0 * 68 + n8 * 8 + 2 * qc) = s0;
                *(float2*)(act + r1 * 68 + n8 * 8 + 2 * qc) = s1;
            }
        }
        __syncthreads();

        // ---- S4: LN2 -> h2; store g_h2; gate score (2 threads/token) ----
        {
            int t = tbase + prow;
            float x[32];
            const float4* ar = (const float4*)(act + prow * 68 + phalf * 32);
            int pb = phalf * 32;
            float sum = 0.f;
#pragma unroll
            for (int c = 0; c < 8; c++) {
                float4 a = ar[c];
                x[4*c] = a.x; x[4*c+1] = a.y; x[4*c+2] = a.z; x[4*c+3] = a.w;
                sum += a.x + a.y + a.z + a.w;
            }
            sum += __shfl_xor_sync(0xffffffffu, sum, 1);
            float m = sum * (1.f/64.f);
            float var = 0.f;
#pragma unroll
            for (int j = 0; j < 32; j++) { float d = x[j] - m; var += d * d; }
            var += __shfl_xor_sync(0xffffffffu, var, 1);
            float rstd = rsqrtf(var * (1.f/64.f) + 1e-5f);
            float4* aw = (float4*)(act + prow * 68 + phalf * 32);
            float4* hg = (float4*)(g_h2 + (size_t)t * 64 + phalf * 32);
            float g = 0.f;
#pragma unroll
            for (int c = 0; c < 8; c++) {
                float4 o;
                o.x = (x[4*c]   - m) * rstd * prm[448+pb+4*c]   + prm[512+pb+4*c];
                o.y = (x[4*c+1] - m) * rstd * prm[448+pb+4*c+1] + prm[512+pb+4*c+1];
                o.z = (x[4*c+2] - m) * rstd * prm[448+pb+4*c+2] + prm[512+pb+4*c+2];
                o.w = (x[4*c+3] - m) * rstd * prm[448+pb+4*c+3] + prm[512+pb+4*c+3];
                aw[c] = o;
                hg[c] = o;
                g += o.x * prm[576+pb+4*c] + o.y * prm[576+pb+4*c+1]
                   + o.z * prm[576+pb+4*c+2] + o.w * prm[576+pb+4*c+3];
            }
            g += __shfl_xor_sync(0xffffffffu, g, 1);
            if (phalf == 0) g_gs[t] = g + prm[640];
        }
        __syncthreads();

        // ---- S5: LM logits (1-pass tf32) ----
        {
            u32 ah[8][4];
#pragma unroll
            for (int kk = 0; kk < 8; kk++) {
                ah[kk][0] = f2tf32(act[r0 * 68 + kk * 8 + qc]);
                ah[kk][1] = f2tf32(act[r1 * 68 + kk * 8 + qc]);
                ah[kk][2] = f2tf32(act[r0 * 68 + kk * 8 + qc + 4]);
                ah[kk][3] = f2tf32(act[r1 * 68 + kk * 8 + qc + 4]);
            }
            __syncwarp();
#pragma unroll
            for (int n8 = 0; n8 < 8; n8++) {
                float c0 = 0.f, c1 = 0.f, c2 = 0.f, c3 = 0.f;
                int wrow = (n8 * 8 + qr) * 68 + 2 * qc;
#pragma unroll
                for (int kk = 0; kk < 8; kk++) {
                    uint2 bh = *(const uint2*)(LMH + wrow + kk * 8);
                    mma_tf32(c0, c1, c2, c3, ah[kk][0], ah[kk][1], ah[kk][2], ah[kk][3], bh.x, bh.y);
                }
                float bb0 = prm[256 + n8 * 8 + 2 * qc];
                float bb1 = prm[256 + n8 * 8 + 2 * qc + 1];
                *(float2*)(act + r0 * 68 + n8 * 8 + 2 * qc) = make_float2(c0 + bb0, c1 + bb1);
                *(float2*)(act + r1 * 68 + n8 * 8 + 2 * qc) = make_float2(c2 + bb0, c3 + bb1);
            }
        }
        __syncthreads();

        // ---- S6: per-token LSE + loss (2 threads/token) ----
        {
            int t = tbase + prow;
            int l = t & 511;
            int nt = seq[(l < 511) ? (t + 1) : t];
            const float* lr = act + prow * 68 + phalf * 32;
            float se = 0.f;
#pragma unroll
            for (int j = 0; j < 16; j++) {
                float p0, p1;
                fexp2(E, lr[2*j], lr[2*j+1], p0, p1);
                se += p0 + p1;
            }
            se += __shfl_xor_sync(0xffffffffu, se, 1);
            float lgtp = (phalf == (nt >> 5)) ? lr[nt & 31] : 0.f;
            float lgt = lgtp + __shfl_xor_sync(0xffffffffu, lgtp, 1);
            if (phalf == 0)
                out_tok[t] = (l < 511) ? (logf(se) - lgt) : 0.f;
        }
    }
}

// -------------------- K4: top-8 gate + memory read + task loss (128 thr/b) --
__global__ void __launch_bounds__(128) k4_memory(
        const float* __restrict__ qembed,
        const float* __restrict__ qpW, const float* __restrict__ qpb,
        const float* __restrict__ opW, const float* __restrict__ opb,
        const int* __restrict__ query, const int* __restrict__ target) {
    int b = blockIdx.x, tid = threadIdx.x, lane = tid & 31, w = tid >> 5;
    __shared__ float cand_v[32]; __shared__ int cand_i[32];
    __shared__ float qh_s[64], qp_s[64], rs_s[8], rw_s[8], retr[64], lg_s[64];
    __shared__ int idx_s[KSLOT];
    float sc[4]; int si[4];
#pragma unroll
    for (int u = 0; u < 4; u++) {
        int i = w * 128 + u * 32 + lane;
        sc[u] = g_gs[b*512 + i]; si[u] = i;
    }
    if (tid < 64) qh_s[tid] = qembed[(size_t)query[b]*64 + tid];
    // phase 1: per-warp top-8 (registers only)
#pragma unroll 1
    for (int it = 0; it < 8; it++) {
        float best = -1e30f; int bi = 1 << 30;
#pragma unroll
        for (int u = 0; u < 4; u++)
            if (sc[u] > best) { best = sc[u]; bi = si[u]; }
#pragma unroll
        for (int o = 16; o; o >>= 1) {
            float ov = __shfl_xor_sync(0xffffffffu, best, o);
            int   oi = __shfl_xor_sync(0xffffffffu, bi, o);
            if (ov > best || (ov == best && oi < bi)) { best = ov; bi = oi; }
        }
        if (lane == 0) { cand_v[w*8 + it] = best; cand_i[w*8 + it] = bi; }
#pragma unroll
        for (int u = 0; u < 4; u++)
            if (si[u] == bi) sc[u] = -1e30f;
    }
    __syncthreads();
    // phase 2: warp 0 merges 32 candidates
    if (w == 0) {
        float v = cand_v[lane]; int ii = cand_i[lane];
#pragma unroll 1
        for (int it = 0; it < 8; it++) {
            float best = v; int bi = ii;
#pragma unroll
            for (int o = 16; o; o >>= 1) {
                float ov = __shfl_xor_sync(0xffffffffu, best, o);
                int   oi = __shfl_xor_sync(0xffffffffu, bi, o);
                if (ov > best || (ov == best && oi < bi)) { best = ov; bi = oi; }
            }
            if (lane == 0) idx_s[it] = bi;
            if (ii == bi) v = -1e30f;
        }
    }
    __syncthreads();
    // qp = qp_W @ qh + qp_b  (2 threads per output)
    {
        int o = tid >> 1, hf = tid & 1;
        const float4* wr = (const float4*)(qpW + o*64 + hf*32);
        const float4* qv = (const float4*)(qh_s + hf*32);
        float s = 0.f;
#pragma unroll
        for (int c = 0; c < 8; c++) {
            float4 wv = wr[c], qq = qv[c];
            s = fmaf(wv.x, qq.x, s); s = fmaf(wv.y, qq.y, s);
            s = fmaf(wv.z, qq.z, s); s = fmaf(wv.w, qq.w, s);
        }
        s += __shfl_xor_sync(0xffffffffu, s, 1);
        if (hf == 0) qp_s[o] = s + qpb[o];
    }
    __syncthreads();
    if (tid < 16) {
        int k = tid >> 1, hf = tid & 1;
        const float4* hr = (const float4*)(g_h2 + ((size_t)b*512 + idx_s[k]) * 64 + hf*32);
        const float4* qv = (const float4*)(qp_s + hf*32);
        float s = 0.f;
#pragma unroll
        for (int c = 0; c < 8; c++) {
            float4 hv = hr[c], qq = qv[c];
            s = fmaf(hv.x, qq.x, s); s = fmaf(hv.y, qq.y, s);
            s = fmaf(hv.z, qq.z, s); s = fmaf(hv.w, qq.w, s);
        }
        s += __shfl_xor_sync(0xffffu, s, 1);
        if (hf == 0) rs_s[k] = s * 0.125f;
    }
    __syncthreads();
    if (tid == 0) {
        float mx = -1e30f;
        for (int k = 0; k < KSLOT; k++) mx = fmaxf(mx, rs_s[k]);
        float s = 0.f; float e[KSLOT];
        for (int k = 0; k < KSLOT; k++) { e[k] = expf(rs_s[k] - mx); s += e[k]; }
        for (int k = 0; k < KSLOT; k++) rw_s[k] = e[k] / s;
    }
    __syncthreads();
    if (tid < 64) {
        float s = 0.f;
        for (int k = 0; k < KSLOT; k++)
            s = fmaf(rw_s[k], g_h2[((size_t)b*512 + idx_s[k])*64 + tid], s);
        retr[tid] = s;
    }
    __syncthreads();
    {
        int o = tid >> 1, hf = tid & 1;
        const float4* wr = (const float4*)(opW + o*64 + hf*32);
        const float4* rv = (const float4*)(retr + hf*32);
        float s = 0.f;
#pragma unroll
        for (int c = 0; c < 8; c++) {
            float4 wv = wr[c], rr = rv[c];
            s = fmaf(wv.x, rr.x, s); s = fmaf(wv.y, rr.y, s);
            s = fmaf(wv.z, rr.z, s); s = fmaf(wv.w, rr.w, s);
        }
        s += __shfl_xor_sync(0xffffffffu, s, 1);
        if (hf == 0) lg_s[o] = s + opb[o];
    }
    __syncthreads();
    if (tid < 32) {
        float l0 = lg_s[lane], l1 = lg_s[lane + 32];
        float mx = warp_max(fmaxf(l0, l1));
        float s = warp_sum(expf(l0 - mx) + expf(l1 - mx));
        if (lane == 0) g_tl[b] = (mx + logf(s)) - lg_s[target[b]];
    }
}

// -------------------- K5: deterministic mean of task losses -----------------
__global__ void k5_mean(float* __restrict__ out) {
    __shared__ float s[256];
    int tid = threadIdx.x;
    s[tid] = g_tl[tid];
    __syncthreads();
    for (int st = 128; st; st >>= 1) {
        if (tid < st) s[tid] += s[tid + st];
        __syncthreads();
    }
    if (tid == 0) out[0] = s[0] * (1.f / 256.f);
}

// -------------------- launch ------------------------------------------------
extern "C" void kernel_launch(void* const* d_in, const int* in_sizes, int n_in,
                              void* d_out, int out_size) {
    const float* embed  = (const float*)d_in[0];
    const float* qembed = (const float*)d_in[1];
    const float* W_in   = (const float*)d_in[2];
    const float* b_in   = (const float*)d_in[3];
    const float* W_out  = (const float*)d_in[4];
    const float* b_out  = (const float*)d_in[5];
    const float* ln1g   = (const float*)d_in[6];
    const float* ln1b   = (const float*)d_in[7];
    const float* W1     = (const float*)d_in[8];
    const float* b1     = (const float*)d_in[9];
    const float* W2     = (const float*)d_in[10];
    const float* b2     = (const float*)d_in[11];
    const float* ln2g   = (const float*)d_in[12];
    const float* ln2b   = (const float*)d_in[13];
    const float* lmW    = (const float*)d_in[14];
    const float* lmb    = (const float*)d_in[15];
    const float* gateW  = (const float*)d_in[16];
    const float* gateb  = (const float*)d_in[17];
    const float* qpW    = (const float*)d_in[18];
    const float* qpb    = (const float*)d_in[19];
    const float* opW    = (const float*)d_in[20];
    const float* opb    = (const float*)d_in[21];
    const int*   seq    = (const int*)d_in[22];
    const int*   query  = (const int*)d_in[23];
    const int*   target = (const int*)d_in[24];
    float* out = (float*)d_out;
    float* out_tok = out + (out_size - BB * LL);

    size_t sm1 = K1_SMW * sizeof(u32);
    size_t sm2 = K2_SMB;
    size_t sm3 = K3_SMW * sizeof(u32);
    cudaFuncSetAttribute(k1_embed_qkv, cudaFuncAttributeMaxDynamicSharedMemorySize, (int)sm1);
    cudaFuncSetAttribute(k2_attn,      cudaFuncAttributeMaxDynamicSharedMemorySize, (int)sm2);
    cudaFuncSetAttribute(k3_epilogue,  cudaFuncAttributeMaxDynamicSharedMemorySize, (int)sm3);

    k1_embed_qkv<<<BB*LL/256, 512, sm1>>>(embed, W_in, b_in, seq);
    k2_attn<<<BB*NHEAD*4, 256, sm2>>>();
    k3_epilogue<<<BB*LL/256, 256, sm3>>>(embed, W_out, b_out, ln1g, ln1b, W1, b1,
                                         W2, b2, ln2g, ln2b, lmW, lmb, gateW, gateb,
                                         seq, out_tok);
    k4_memory<<<BB, 128>>>(qembed, qpW, qpb, opW, opb, query, target);
    k5_mean<<<1, 256>>>(out);
}